// round 1
// baseline (speedup 1.0000x reference)
#include <cuda_runtime.h>
#include <math.h>

// Problem constants: B=2, T=2048, C=1024, H=16, HD=64
constexpr int NB  = 2;
constexpr int NT  = 2048;
constexpr int NC  = 1024;
constexpr int NH  = 16;
constexpr int NHD = 64;
constexpr int NM  = NB * NT;           // 4096 rows
constexpr int NPAIRS = NM * NH * (NHD / 2);  // rope pairs per tensor

// Scratch (static device globals: allocation-free)
__device__ float g_q [NM * NC];
__device__ float g_k [NM * NC];
__device__ float g_v [NM * NC];
__device__ float g_ao[NM * NC];

// ---------------------------------------------------------------------------
// GEMM: C[m][n] = sum_k A[m][k] * B[n][k]   (A: MxK row-major, B: NxK row-major)
// 64x64 block tile, BK=16, 256 threads, 4x4 register tile per thread.
// ---------------------------------------------------------------------------
__global__ void gemm_nt_kernel(const float* __restrict__ A,
                               const float* __restrict__ B,
                               float* __restrict__ C,
                               int M, int N, int K) {
    __shared__ float As[16][68];
    __shared__ float Bs[16][68];

    const int tx = threadIdx.x & 15;
    const int ty = threadIdx.x >> 4;
    const int m0 = blockIdx.y << 6;
    const int n0 = blockIdx.x << 6;

    const int lr = threadIdx.x >> 2;        // 0..63  (tile row)
    const int lk = (threadIdx.x & 3) << 2;  // 0,4,8,12

    const float* Ap = A + (size_t)(m0 + lr) * K + lk;
    const float* Bp = B + (size_t)(n0 + lr) * K + lk;

    float acc[4][4] = {};

    for (int k0 = 0; k0 < K; k0 += 16) {
        float4 av = *(const float4*)(Ap + k0);
        float4 bv = *(const float4*)(Bp + k0);
        As[lk + 0][lr] = av.x; As[lk + 1][lr] = av.y;
        As[lk + 2][lr] = av.z; As[lk + 3][lr] = av.w;
        Bs[lk + 0][lr] = bv.x; Bs[lk + 1][lr] = bv.y;
        Bs[lk + 2][lr] = bv.z; Bs[lk + 3][lr] = bv.w;
        __syncthreads();

#pragma unroll
        for (int kk = 0; kk < 16; kk++) {
            float4 a = *(const float4*)&As[kk][ty << 2];
            float4 b = *(const float4*)&Bs[kk][tx << 2];
            float ar[4] = {a.x, a.y, a.z, a.w};
            float br[4] = {b.x, b.y, b.z, b.w};
#pragma unroll
            for (int i = 0; i < 4; i++)
#pragma unroll
                for (int j = 0; j < 4; j++)
                    acc[i][j] += ar[i] * br[j];
        }
        __syncthreads();
    }

#pragma unroll
    for (int i = 0; i < 4; i++) {
        float4 o = make_float4(acc[i][0], acc[i][1], acc[i][2], acc[i][3]);
        *(float4*)&C[(size_t)(m0 + (ty << 2) + i) * N + n0 + (tx << 2)] = o;
    }
}

// ---------------------------------------------------------------------------
// RoPE (interleaved pairs) applied in-place to q and k.
// Layout: tensor[(b*T + t)*C + h*64 + d]; pair (2i, 2i+1), angle = ang[t][i].
// ---------------------------------------------------------------------------
__global__ void rope_kernel(float* __restrict__ q, float* __restrict__ k,
                            const float* __restrict__ cosb,
                            const float* __restrict__ sinb) {
    int idx = blockIdx.x * blockDim.x + threadIdx.x;
    if (idx >= NPAIRS) return;
    int i = idx & 31;
    int h = (idx >> 5) & (NH - 1);
    int m = idx >> 9;           // row in [0, NM)
    int t = m & (NT - 1);

    float c = cosb[t * 32 + i];
    float s = sinb[t * 32 + i];

    size_t base = (size_t)m * NC + h * NHD + 2 * i;

    float2 qv = *(float2*)&q[base];
    float2 kv = *(float2*)&k[base];
    float2 qo, ko;
    qo.x = qv.x * c - qv.y * s;
    qo.y = qv.x * s + qv.y * c;
    ko.x = kv.x * c - kv.y * s;
    ko.y = kv.x * s + kv.y * c;
    *(float2*)&q[base] = qo;
    *(float2*)&k[base] = ko;
}

// ---------------------------------------------------------------------------
// Flash attention, fp32, causal. One block = (q-tile of 64, head, batch).
// BM=BN=HD=64, 256 threads (16x16), 4x4 register tiles, online softmax.
// Dynamic smem: Qs,Ks,Vs,Ps each 64x68 floats = 69632 bytes.
// ---------------------------------------------------------------------------
constexpr int FPAD = 68;
constexpr int FLASH_SMEM = 4 * 64 * FPAD * (int)sizeof(float);

__global__ void flash_kernel(const float* __restrict__ q,
                             const float* __restrict__ k,
                             const float* __restrict__ v,
                             float* __restrict__ o) {
    extern __shared__ float smem[];
    float* Qs = smem;
    float* Ks = smem + 64 * FPAD;
    float* Vs = smem + 2 * 64 * FPAD;
    float* Ps = smem + 3 * 64 * FPAD;

    const int bx = blockIdx.x;       // q tile index
    const int h  = blockIdx.y;
    const int b  = blockIdx.z;
    const int m0 = bx << 6;

    const int tx = threadIdx.x & 15;
    const int ty = threadIdx.x >> 4;

    const int lr  = threadIdx.x >> 2;          // 0..63 tile row
    const int ld0 = (threadIdx.x & 3) << 4;    // 0,16,32,48

    // Load Q tile transposed (Qs[d][r]), fold in 1/sqrt(HD) = 0.125
    {
        const float* qrow = &q[(size_t)(b * NT + m0 + lr) * NC + h * NHD];
#pragma unroll
        for (int u = 0; u < 4; u++) {
            int d = ld0 + 4 * u;
            float4 t4 = *(const float4*)&qrow[d];
            Qs[(d + 0) * FPAD + lr] = t4.x * 0.125f;
            Qs[(d + 1) * FPAD + lr] = t4.y * 0.125f;
            Qs[(d + 2) * FPAD + lr] = t4.z * 0.125f;
            Qs[(d + 3) * FPAD + lr] = t4.w * 0.125f;
        }
    }

    float o_acc[4][4] = {};
    float rmax[4], rsum[4];
#pragma unroll
    for (int i = 0; i < 4; i++) { rmax[i] = -1e30f; rsum[i] = 0.0f; }

    __syncthreads();

    for (int nt = 0; nt <= bx; nt++) {
        // Load K transposed, V direct
        {
            const float* krow = &k[(size_t)(b * NT + (nt << 6) + lr) * NC + h * NHD];
            const float* vrow = &v[(size_t)(b * NT + (nt << 6) + lr) * NC + h * NHD];
#pragma unroll
            for (int u = 0; u < 4; u++) {
                int d = ld0 + 4 * u;
                float4 t4 = *(const float4*)&krow[d];
                Ks[(d + 0) * FPAD + lr] = t4.x;
                Ks[(d + 1) * FPAD + lr] = t4.y;
                Ks[(d + 2) * FPAD + lr] = t4.z;
                Ks[(d + 3) * FPAD + lr] = t4.w;
                float4 v4 = *(const float4*)&vrow[d];
                *(float4*)&Vs[lr * FPAD + d] = v4;
            }
        }
        __syncthreads();

        // S = (Q/8) @ K^T, 64x64 tile, 4x4 per thread
        float s_t[4][4] = {};
#pragma unroll 8
        for (int kk = 0; kk < 64; kk++) {
            float4 a = *(const float4*)&Qs[kk * FPAD + (ty << 2)];
            float4 bb = *(const float4*)&Ks[kk * FPAD + (tx << 2)];
            float ar[4] = {a.x, a.y, a.z, a.w};
            float br[4] = {bb.x, bb.y, bb.z, bb.w};
#pragma unroll
            for (int i = 0; i < 4; i++)
#pragma unroll
                for (int j = 0; j < 4; j++)
                    s_t[i][j] += ar[i] * br[j];
        }

        // Causal mask on diagonal tile (key index > query index)
        if (nt == bx) {
#pragma unroll
            for (int i = 0; i < 4; i++)
#pragma unroll
                for (int j = 0; j < 4; j++)
                    if ((tx << 2) + j > (ty << 2) + i) s_t[i][j] = -1e30f;
        }

        // Online softmax per row (row group = 16 lanes, same ty)
#pragma unroll
        for (int i = 0; i < 4; i++) {
            float tmax = fmaxf(fmaxf(s_t[i][0], s_t[i][1]),
                               fmaxf(s_t[i][2], s_t[i][3]));
#pragma unroll
            for (int off = 8; off >= 1; off >>= 1)
                tmax = fmaxf(tmax, __shfl_xor_sync(0xffffffffu, tmax, off));

            float nm = fmaxf(rmax[i], tmax);
            float corr = __expf(rmax[i] - nm);
            rmax[i] = nm;
            rsum[i] *= corr;
#pragma unroll
            for (int j = 0; j < 4; j++) o_acc[i][j] *= corr;

            float ps = 0.0f;
#pragma unroll
            for (int j = 0; j < 4; j++) {
                float p = __expf(s_t[i][j] - nm);
                s_t[i][j] = p;
                ps += p;
            }
#pragma unroll
            for (int off = 8; off >= 1; off >>= 1)
                ps += __shfl_xor_sync(0xffffffffu, ps, off);
            rsum[i] += ps;
        }

        // Stage P transposed: Ps[n][r]
#pragma unroll
        for (int i = 0; i < 4; i++)
#pragma unroll
            for (int j = 0; j < 4; j++)
                Ps[((tx << 2) + j) * FPAD + (ty << 2) + i] = s_t[i][j];
        __syncthreads();

        // O += P @ V
#pragma unroll 8
        for (int kk = 0; kk < 64; kk++) {
            float4 p4 = *(const float4*)&Ps[kk * FPAD + (ty << 2)];
            float4 v4 = *(const float4*)&Vs[kk * FPAD + (tx << 2)];
            float pr[4] = {p4.x, p4.y, p4.z, p4.w};
            float vr[4] = {v4.x, v4.y, v4.z, v4.w};
#pragma unroll
            for (int i = 0; i < 4; i++)
#pragma unroll
                for (int j = 0; j < 4; j++)
                    o_acc[i][j] += pr[i] * vr[j];
        }
        __syncthreads();  // protect Ks/Vs/Ps before next iteration
    }

    // Epilogue: normalize and store
#pragma unroll
    for (int i = 0; i < 4; i++) {
        float inv = 1.0f / rsum[i];
        float4 r4 = make_float4(o_acc[i][0] * inv, o_acc[i][1] * inv,
                                o_acc[i][2] * inv, o_acc[i][3] * inv);
        *(float4*)&o[(size_t)(b * NT + m0 + (ty << 2) + i) * NC
                     + h * NHD + (tx << 2)] = r4;
    }
}

// ---------------------------------------------------------------------------
extern "C" void kernel_launch(void* const* d_in, const int* in_sizes, int n_in,
                              void* d_out, int out_size) {
    const float* x    = (const float*)d_in[0];
    const float* Wq   = (const float*)d_in[1];
    const float* Wk   = (const float*)d_in[2];
    const float* Wv   = (const float*)d_in[3];
    const float* Wo   = (const float*)d_in[4];
    const float* cosb = (const float*)d_in[5];
    const float* sinb = (const float*)d_in[6];
    float* out = (float*)d_out;

    float *qp, *kp, *vp, *aop;
    cudaGetSymbolAddress((void**)&qp,  g_q);
    cudaGetSymbolAddress((void**)&kp,  g_k);
    cudaGetSymbolAddress((void**)&vp,  g_v);
    cudaGetSymbolAddress((void**)&aop, g_ao);

    dim3 gblk(256);
    dim3 ggrid(NC / 64, NM / 64);

    gemm_nt_kernel<<<ggrid, gblk>>>(x, Wq, qp, NM, NC, NC);
    gemm_nt_kernel<<<ggrid, gblk>>>(x, Wk, kp, NM, NC, NC);
    gemm_nt_kernel<<<ggrid, gblk>>>(x, Wv, vp, NM, NC, NC);

    rope_kernel<<<(NPAIRS + 255) / 256, 256>>>(qp, kp, cosb, sinb);

    cudaFuncSetAttribute(flash_kernel,
                         cudaFuncAttributeMaxDynamicSharedMemorySize,
                         FLASH_SMEM);
    flash_kernel<<<dim3(NT / 64, NH, NB), 256, FLASH_SMEM>>>(qp, kp, vp, aop);

    gemm_nt_kernel<<<ggrid, gblk>>>(aop, Wo, out, NM, NC, NC);
}

// round 3
// speedup vs baseline: 1.1764x; 1.1764x over previous
#include <cuda_runtime.h>
#include <math.h>
#include <cstdint>
#include <mma.h>

using namespace nvcuda;

// Problem constants: B=2, T=2048, C=1024, H=16, HD=64
constexpr int NB  = 2;
constexpr int NT  = 2048;
constexpr int NC  = 1024;
constexpr int NH  = 16;
constexpr int NHD = 64;
constexpr int NM  = NB * NT;           // 4096 rows
constexpr int NPAIRS = NM * NH * (NHD / 2);

// Scratch (static device globals: allocation-free)
__device__ float g_q [NM * NC];
__device__ float g_k [NM * NC];
__device__ float g_v [NM * NC];
__device__ float g_ao[NM * NC];

__device__ __forceinline__ float to_tf32(float x) {
    uint32_t r;
    asm("cvt.rna.tf32.f32 %0, %1;" : "=r"(r) : "f"(x));
    return __uint_as_float(r);
}

// ===========================================================================
// WMMA tf32 GEMM: C[m][n] = sum_k A[m][k] * B[n][k]
// (A: MxK row-major, B: NxK row-major -> matrix_b col_major over B^T)
// CTA tile 128x128, K-chunk 32, 8 warps, warp tile 32x64 (2x4 m16n16k8 frags).
// Double-buffered padded smem (ldm=36), prefetch overlaps mma phase.
// ===========================================================================
constexpr int GLD = 36;                           // padded smem leading dim
constexpr int GEMM_SMEM = 2 * 2 * 128 * GLD * 4;  // 73728 bytes

__global__ void __launch_bounds__(256)
gemm_wmma_kernel(const float* __restrict__ A, const float* __restrict__ B,
                 float* __restrict__ C, int M, int N, int K) {
    extern __shared__ float smemf[];
    float* As = smemf;                  // [2][128*GLD]
    float* Bs = smemf + 2 * 128 * GLD;  // [2][128*GLD]

    const int tid = threadIdx.x;
    const int w   = tid >> 5;
    const int m0  = blockIdx.y << 7;
    const int n0  = blockIdx.x << 7;
    const int mw  = (w & 3) << 5;       // warp m offset (0,32,64,96)
    const int nw  = (w >> 2) << 6;      // warp n offset (0,64)

    // staging: thread -> row r (0..127), k half (0 or 16)
    const int r  = tid >> 1;
    const int kh = (tid & 1) << 4;

    const float* Ap = A + (size_t)(m0 + r) * K + kh;
    const float* Bp = B + (size_t)(n0 + r) * K + kh;
    float* AsRow = &As[r * GLD + kh];
    float* BsRow = &Bs[r * GLD + kh];

    wmma::fragment<wmma::accumulator, 16, 16, 8, float> acc[2][4];
#pragma unroll
    for (int im = 0; im < 2; im++)
#pragma unroll
        for (int in = 0; in < 4; in++)
            wmma::fill_fragment(acc[im][in], 0.0f);

    const int KC = K >> 5;   // number of 32-wide K chunks

    auto stage = [&](int i, int s) {
        const int k0 = i << 5;
        const int so = s * 128 * GLD;
#pragma unroll
        for (int u = 0; u < 4; u++) {
            float4 a = *(const float4*)(Ap + k0 + 4 * u);
            float* pa = AsRow + so + 4 * u;
            pa[0] = to_tf32(a.x); pa[1] = to_tf32(a.y);
            pa[2] = to_tf32(a.z); pa[3] = to_tf32(a.w);
            float4 b = *(const float4*)(Bp + k0 + 4 * u);
            float* pb = BsRow + so + 4 * u;
            pb[0] = to_tf32(b.x); pb[1] = to_tf32(b.y);
            pb[2] = to_tf32(b.z); pb[3] = to_tf32(b.w);
        }
    };

    stage(0, 0);
    __syncthreads();

    for (int i = 0; i < KC; i++) {
        const int s = i & 1;
        if (i + 1 < KC) stage(i + 1, s ^ 1);

        const float* AsB = As + s * 128 * GLD;
        const float* BsB = Bs + s * 128 * GLD;
#pragma unroll
        for (int ks = 0; ks < 4; ks++) {
            wmma::fragment<wmma::matrix_a, 16, 16, 8,
                           wmma::precision::tf32, wmma::row_major> af[2];
            wmma::fragment<wmma::matrix_b, 16, 16, 8,
                           wmma::precision::tf32, wmma::col_major> bf[4];
#pragma unroll
            for (int im = 0; im < 2; im++)
                wmma::load_matrix_sync(af[im],
                    AsB + (mw + 16 * im) * GLD + ks * 8, GLD);
#pragma unroll
            for (int in = 0; in < 4; in++)
                wmma::load_matrix_sync(bf[in],
                    BsB + (nw + 16 * in) * GLD + ks * 8, GLD);
#pragma unroll
            for (int im = 0; im < 2; im++)
#pragma unroll
                for (int in = 0; in < 4; in++)
                    wmma::mma_sync(acc[im][in], af[im], bf[in], acc[im][in]);
        }
        __syncthreads();
    }

#pragma unroll
    for (int im = 0; im < 2; im++)
#pragma unroll
        for (int in = 0; in < 4; in++)
            wmma::store_matrix_sync(
                &C[(size_t)(m0 + mw + 16 * im) * N + n0 + nw + 16 * in],
                acc[im][in], N, wmma::mem_row_major);
}

// ===========================================================================
// RoPE (unchanged)
// ===========================================================================
__global__ void rope_kernel(float* __restrict__ q, float* __restrict__ k,
                            const float* __restrict__ cosb,
                            const float* __restrict__ sinb) {
    int idx = blockIdx.x * blockDim.x + threadIdx.x;
    if (idx >= NPAIRS) return;
    int i = idx & 31;
    int h = (idx >> 5) & (NH - 1);
    int m = idx >> 9;
    int t = m & (NT - 1);

    float c = cosb[t * 32 + i];
    float s = sinb[t * 32 + i];

    size_t base = (size_t)m * NC + h * NHD + 2 * i;

    float2 qv = *(float2*)&q[base];
    float2 kv = *(float2*)&k[base];
    float2 qo, ko;
    qo.x = qv.x * c - qv.y * s;
    qo.y = qv.x * s + qv.y * c;
    ko.x = kv.x * c - kv.y * s;
    ko.y = kv.x * s + kv.y * c;
    *(float2*)&q[base] = qo;
    *(float2*)&k[base] = ko;
}

// ===========================================================================
// Flash attention fp32 (verified R1 version, unchanged)
// ===========================================================================
constexpr int FPAD = 68;
constexpr int FLASH_SMEM = 4 * 64 * FPAD * (int)sizeof(float);

__global__ void flash_kernel(const float* __restrict__ q,
                             const float* __restrict__ k,
                             const float* __restrict__ v,
                             float* __restrict__ o) {
    extern __shared__ float smemf[];
    float* Qs = smemf;
    float* Ks = smemf + 64 * FPAD;
    float* Vs = smemf + 2 * 64 * FPAD;
    float* Ps = smemf + 3 * 64 * FPAD;

    const int bx = blockIdx.x;
    const int h  = blockIdx.y;
    const int b  = blockIdx.z;
    const int m0 = bx << 6;

    const int tx = threadIdx.x & 15;
    const int ty = threadIdx.x >> 4;

    const int lr  = threadIdx.x >> 2;
    const int ld0 = (threadIdx.x & 3) << 4;

    {
        const float* qrow = &q[(size_t)(b * NT + m0 + lr) * NC + h * NHD];
#pragma unroll
        for (int u = 0; u < 4; u++) {
            int d = ld0 + 4 * u;
            float4 t4 = *(const float4*)&qrow[d];
            Qs[(d + 0) * FPAD + lr] = t4.x * 0.125f;
            Qs[(d + 1) * FPAD + lr] = t4.y * 0.125f;
            Qs[(d + 2) * FPAD + lr] = t4.z * 0.125f;
            Qs[(d + 3) * FPAD + lr] = t4.w * 0.125f;
        }
    }

    float o_acc[4][4] = {};
    float rmax[4], rsum[4];
#pragma unroll
    for (int i = 0; i < 4; i++) { rmax[i] = -1e30f; rsum[i] = 0.0f; }

    __syncthreads();

    for (int nt = 0; nt <= bx; nt++) {
        {
            const float* krow = &k[(size_t)(b * NT + (nt << 6) + lr) * NC + h * NHD];
            const float* vrow = &v[(size_t)(b * NT + (nt << 6) + lr) * NC + h * NHD];
#pragma unroll
            for (int u = 0; u < 4; u++) {
                int d = ld0 + 4 * u;
                float4 t4 = *(const float4*)&krow[d];
                Ks[(d + 0) * FPAD + lr] = t4.x;
                Ks[(d + 1) * FPAD + lr] = t4.y;
                Ks[(d + 2) * FPAD + lr] = t4.z;
                Ks[(d + 3) * FPAD + lr] = t4.w;
                float4 v4 = *(const float4*)&vrow[d];
                *(float4*)&Vs[lr * FPAD + d] = v4;
            }
        }
        __syncthreads();

        float s_t[4][4] = {};
#pragma unroll 8
        for (int kk = 0; kk < 64; kk++) {
            float4 a = *(const float4*)&Qs[kk * FPAD + (ty << 2)];
            float4 bb = *(const float4*)&Ks[kk * FPAD + (tx << 2)];
            float ar[4] = {a.x, a.y, a.z, a.w};
            float br[4] = {bb.x, bb.y, bb.z, bb.w};
#pragma unroll
            for (int i = 0; i < 4; i++)
#pragma unroll
                for (int j = 0; j < 4; j++)
                    s_t[i][j] += ar[i] * br[j];
        }

        if (nt == bx) {
#pragma unroll
            for (int i = 0; i < 4; i++)
#pragma unroll
                for (int j = 0; j < 4; j++)
                    if ((tx << 2) + j > (ty << 2) + i) s_t[i][j] = -1e30f;
        }

#pragma unroll
        for (int i = 0; i < 4; i++) {
            float tmax = fmaxf(fmaxf(s_t[i][0], s_t[i][1]),
                               fmaxf(s_t[i][2], s_t[i][3]));
#pragma unroll
            for (int off = 8; off >= 1; off >>= 1)
                tmax = fmaxf(tmax, __shfl_xor_sync(0xffffffffu, tmax, off));

            float nm = fmaxf(rmax[i], tmax);
            float corr = __expf(rmax[i] - nm);
            rmax[i] = nm;
            rsum[i] *= corr;
#pragma unroll
            for (int j = 0; j < 4; j++) o_acc[i][j] *= corr;

            float ps = 0.0f;
#pragma unroll
            for (int j = 0; j < 4; j++) {
                float p = __expf(s_t[i][j] - nm);
                s_t[i][j] = p;
                ps += p;
            }
#pragma unroll
            for (int off = 8; off >= 1; off >>= 1)
                ps += __shfl_xor_sync(0xffffffffu, ps, off);
            rsum[i] += ps;
        }

#pragma unroll
        for (int i = 0; i < 4; i++)
#pragma unroll
            for (int j = 0; j < 4; j++)
                Ps[((tx << 2) + j) * FPAD + (ty << 2) + i] = s_t[i][j];
        __syncthreads();

#pragma unroll 8
        for (int kk = 0; kk < 64; kk++) {
            float4 p4 = *(const float4*)&Ps[kk * FPAD + (ty << 2)];
            float4 v4 = *(const float4*)&Vs[kk * FPAD + (tx << 2)];
            float pr[4] = {p4.x, p4.y, p4.z, p4.w};
            float vr[4] = {v4.x, v4.y, v4.z, v4.w};
#pragma unroll
            for (int i = 0; i < 4; i++)
#pragma unroll
                for (int j = 0; j < 4; j++)
                    o_acc[i][j] += pr[i] * vr[j];
        }
        __syncthreads();
    }

#pragma unroll
    for (int i = 0; i < 4; i++) {
        float inv = 1.0f / rsum[i];
        float4 r4 = make_float4(o_acc[i][0] * inv, o_acc[i][1] * inv,
                                o_acc[i][2] * inv, o_acc[i][3] * inv);
        *(float4*)&o[(size_t)(b * NT + m0 + (ty << 2) + i) * NC
                     + h * NHD + (tx << 2)] = r4;
    }
}

// ===========================================================================
extern "C" void kernel_launch(void* const* d_in, const int* in_sizes, int n_in,
                              void* d_out, int out_size) {
    const float* x    = (const float*)d_in[0];
    const float* Wq   = (const float*)d_in[1];
    const float* Wk   = (const float*)d_in[2];
    const float* Wv   = (const float*)d_in[3];
    const float* Wo   = (const float*)d_in[4];
    const float* cosb = (const float*)d_in[5];
    const float* sinb = (const float*)d_in[6];
    float* out = (float*)d_out;

    float *qp, *kp, *vp, *aop;
    cudaGetSymbolAddress((void**)&qp,  g_q);
    cudaGetSymbolAddress((void**)&kp,  g_k);
    cudaGetSymbolAddress((void**)&vp,  g_v);
    cudaGetSymbolAddress((void**)&aop, g_ao);

    cudaFuncSetAttribute(gemm_wmma_kernel,
                         cudaFuncAttributeMaxDynamicSharedMemorySize, GEMM_SMEM);

    dim3 ggrid(NC / 128, NM / 128);
    gemm_wmma_kernel<<<ggrid, 256, GEMM_SMEM>>>(x, Wq, qp, NM, NC, NC);
    gemm_wmma_kernel<<<ggrid, 256, GEMM_SMEM>>>(x, Wk, kp, NM, NC, NC);
    gemm_wmma_kernel<<<ggrid, 256, GEMM_SMEM>>>(x, Wv, vp, NM, NC, NC);

    rope_kernel<<<(NPAIRS + 255) / 256, 256>>>(qp, kp, cosb, sinb);

    cudaFuncSetAttribute(flash_kernel,
                         cudaFuncAttributeMaxDynamicSharedMemorySize,
                         FLASH_SMEM);
    flash_kernel<<<dim3(NT / 64, NH, NB), 256, FLASH_SMEM>>>(qp, kp, vp, aop);

    gemm_wmma_kernel<<<ggrid, 256, GEMM_SMEM>>>(aop, Wo, out, NM, NC, NC);
}